// round 5
// baseline (speedup 1.0000x reference)
#include <cuda_runtime.h>
#include <cstdint>

#define NN 100000
#define EE 1600000
#define CC 128
#define EPS_ 1e-5f

// ---------------- scratch (static device globals; no allocation) ----------------
__device__ __align__(16) float g_h[(size_t)NN * CC];     // GEMM output / message features
__device__ __align__(16) float g_agg[(size_t)NN * CC];   // aggregation accumulator
__device__ __align__(16) float g_x1[(size_t)NN * CC];    // x after first block
__device__ float g_deg[NN];
__device__ float g_dinv[NN];
__device__ float g_as[NN];
__device__ float g_ad[NN];
__device__ float g_m[NN];
__device__ float g_den[NN];
__device__ float g_e[EE + NN];             // exp(e - m[dst]) per edge (self at EE+i)
__device__ float g_stats[2 * CC];          // [0,128): col sum; [128,256): col sumsq
__device__ int g_is64;                     // 1 if edges buffer is int64, 0 if int32

// ---------------- edges dtype detection ----------------
// int64 little-endian with values in [0, 1e5): every odd 32-bit word is 0.
// int32 node ids: odd words are random in [0, 1e5) -> all-zero over 512 samples ~ impossible.
__global__ void detect_dtype(const int* __restrict__ e32) {
    __shared__ int ok[256];
    int t = threadIdx.x;
    int all0 = 1;
#pragma unroll
    for (int i = 0; i < 2; i++) {
        int idx = 2 * (t + i * 256) + 1;   // odd words among first 1024 ints (safe: buffer >= 3.2M ints)
        if (e32[idx] != 0) all0 = 0;
    }
    ok[t] = all0;
    __syncthreads();
    for (int s = 128; s; s >>= 1) {
        if (t < s) ok[t] &= ok[t + s];
        __syncthreads();
    }
    if (t == 0) g_is64 = ok[0];
}

__device__ __forceinline__ int edge_src(const int* __restrict__ e32, int t) {
    return g_is64 ? e32[2 * t] : e32[t];
}
__device__ __forceinline__ int edge_dst(const int* __restrict__ e32, int t) {
    return g_is64 ? e32[2 * (EE + t)] : e32[EE + t];
}

// ---------------- degree ----------------
__global__ void init_deg_kernel() {
    int i = blockIdx.x * blockDim.x + threadIdx.x;
    if (i < NN) g_deg[i] = 1.0f;  // self-loop
}

__global__ void count_deg_kernel(const int* __restrict__ e32) {
    int t = blockIdx.x * blockDim.x + threadIdx.x;
    if (t < EE) {
        int d = edge_dst(e32, t);
        atomicAdd(&g_deg[d], 1.0f);
    }
}

__global__ void dinv_kernel() {
    int i = blockIdx.x * blockDim.x + threadIdx.x;
    if (i < NN) g_dinv[i] = rsqrtf(g_deg[i]);
}

// ---------------- GEMM core: g_h[n,128] = IN[n,128] @ W[128,128] ----------------
template <bool FROM_X1>
__device__ __forceinline__ void gemm128_body(const float* __restrict__ Xext,
                                             const float* __restrict__ W) {
    __shared__ float Xs[64][33];
    __shared__ float Ws[32][128];
    const float* X = FROM_X1 ? g_x1 : Xext;
    int row0 = blockIdx.x * 64;
    int tx = threadIdx.x & 15;
    int ty = threadIdx.x >> 4;
    float acc[4][8];
#pragma unroll
    for (int i = 0; i < 4; i++)
#pragma unroll
        for (int j = 0; j < 8; j++) acc[i][j] = 0.f;

    for (int kt = 0; kt < 128; kt += 32) {
#pragma unroll
        for (int i = 0; i < 8; i++) {
            int idx = threadIdx.x + i * 256;
            int r = idx >> 5, c = idx & 31;
            int gr = row0 + r;
            Xs[r][c] = (gr < NN) ? X[(size_t)gr * 128 + kt + c] : 0.f;
        }
#pragma unroll
        for (int i = 0; i < 16; i++) {
            int idx = threadIdx.x + i * 256;
            int r = idx >> 7, c = idx & 127;
            Ws[r][c] = W[(size_t)(kt + r) * 128 + c];
        }
        __syncthreads();
#pragma unroll
        for (int k = 0; k < 32; k++) {
            float a[4], b[8];
#pragma unroll
            for (int i = 0; i < 4; i++) a[i] = Xs[ty * 4 + i][k];
#pragma unroll
            for (int j = 0; j < 8; j++) b[j] = Ws[k][j * 16 + tx];
#pragma unroll
            for (int i = 0; i < 4; i++)
#pragma unroll
                for (int j = 0; j < 8; j++) acc[i][j] = fmaf(a[i], b[j], acc[i][j]);
        }
        __syncthreads();
    }
#pragma unroll
    for (int i = 0; i < 4; i++) {
        int gr = row0 + ty * 4 + i;
        if (gr < NN) {
#pragma unroll
            for (int j = 0; j < 8; j++) g_h[(size_t)gr * 128 + j * 16 + tx] = acc[i][j];
        }
    }
}

__global__ void __launch_bounds__(256) gemm128_A(const float* __restrict__ X,
                                                 const float* __restrict__ W) {
    gemm128_body<false>(X, W);
}
__global__ void __launch_bounds__(256) gemm128_B(const float* __restrict__ W) {
    gemm128_body<true>(nullptr, W);
}

// ---------------- GCN: init agg with self-loop contribution ----------------
__global__ void agg_init_gcn() {
    int idx = blockIdx.x * blockDim.x + threadIdx.x;
    if (idx >= NN * CC) return;
    int n = idx >> 7;
    float di = g_dinv[n];
    g_agg[idx] = g_h[idx] * di * di;
}

// ---------------- GCN scatter over real edges: warp per edge ----------------
__global__ void __launch_bounds__(256) scatter_gcn(const int* __restrict__ e32) {
    int warp = (blockIdx.x * blockDim.x + threadIdx.x) >> 5;
    if (warp >= EE) return;
    int lane = threadIdx.x & 31;
    int s = edge_src(e32, warp);
    int d = edge_dst(e32, warp);
    float norm = g_dinv[s] * g_dinv[d];
    float4 v = ((const float4*)(g_h + (size_t)s * 128))[lane];
    v.x *= norm; v.y *= norm; v.z *= norm; v.w *= norm;
    atomicAdd(((float4*)(g_agg + (size_t)d * 128)) + lane, v);
}

// ---------------- column stats ----------------
__global__ void zero_stats() {
    int i = threadIdx.x;
    if (i < 2 * CC) g_stats[i] = 0.f;
}

__global__ void colstats(const float* __restrict__ bias) {
    __shared__ float s1[256], s2[256];
    int c = threadIdx.x & 127;
    int half = threadIdx.x >> 7;
    float b = bias[c];
    float acc = 0.f, acc2 = 0.f;
    for (int r = blockIdx.x * 2 + half; r < NN; r += gridDim.x * 2) {
        float t = g_agg[(size_t)r * 128 + c] + b;
        acc += t;
        acc2 += t * t;
    }
    s1[threadIdx.x] = acc;
    s2[threadIdx.x] = acc2;
    __syncthreads();
    if (half == 0) {
        atomicAdd(&g_stats[c], s1[c] + s1[c + 128]);
        atomicAdd(&g_stats[128 + c], s2[c] + s2[c + 128]);
    }
}

// ---------------- finalize: GraphNorm + LeakyReLU + residual ----------------
template <bool PHASE_B>
__device__ __forceinline__ void finalize_body(const float* __restrict__ xin_ext,
                                              const float* __restrict__ bias,
                                              const float* __restrict__ gw,
                                              const float* __restrict__ gb,
                                              const float* __restrict__ gms,
                                              float* __restrict__ xout_ext) {
    int idx = blockIdx.x * blockDim.x + threadIdx.x;
    if (idx >= NN * CC) return;
    int c = idx & 127;
    float t = g_agg[idx] + bias[c];
    const float invn = 1.0f / (float)NN;
    float mean = g_stats[c] * invn;
    float a = gms[c] * mean;
    float var = g_stats[128 + c] * invn - 2.f * a * mean + a * a;
    float y = gw[c] * (t - a) * rsqrtf(var + EPS_) + gb[c];
    y = (y >= 0.f) ? y : 0.01f * y;
    float xv = PHASE_B ? g_x1[idx] : xin_ext[idx];
    float r = xv + y;
    if (PHASE_B) xout_ext[idx] = r;
    else g_x1[idx] = r;
}

__global__ void finalize_A(const float* __restrict__ xin, const float* __restrict__ bias,
                           const float* __restrict__ gw, const float* __restrict__ gb,
                           const float* __restrict__ gms) {
    finalize_body<false>(xin, bias, gw, gb, gms, nullptr);
}
__global__ void finalize_B(const float* __restrict__ bias, const float* __restrict__ gw,
                           const float* __restrict__ gb, const float* __restrict__ gms,
                           float* __restrict__ xout) {
    finalize_body<true>(nullptr, bias, gw, gb, gms, xout);
}

// ---------------- GAT attention dots: warp per node ----------------
__global__ void attndot(const float* __restrict__ att_src, const float* __restrict__ att_dst) {
    int warp = (blockIdx.x * blockDim.x + threadIdx.x) >> 5;
    if (warp >= NN) return;
    int lane = threadIdx.x & 31;
    float4 hv = ((const float4*)(g_h + (size_t)warp * 128))[lane];
    float4 av = ((const float4*)att_src)[lane];
    float4 dv = ((const float4*)att_dst)[lane];
    float ps = hv.x * av.x + hv.y * av.y + hv.z * av.z + hv.w * av.w;
    float pd = hv.x * dv.x + hv.y * dv.y + hv.z * dv.z + hv.w * dv.w;
#pragma unroll
    for (int o = 16; o; o >>= 1) {
        ps += __shfl_xor_sync(0xffffffffu, ps, o);
        pd += __shfl_xor_sync(0xffffffffu, pd, o);
    }
    if (lane == 0) {
        g_as[warp] = ps;
        g_ad[warp] = pd;
    }
}

__global__ void init_gat_kernel() {
    int i = blockIdx.x * blockDim.x + threadIdx.x;
    if (i < NN) {
        g_m[i] = -__int_as_float(0x7f800000);  // -inf
        g_den[i] = 0.f;
    }
}

__device__ __forceinline__ void atomicMaxF(float* addr, float value) {
    if (value >= 0.f)
        atomicMax((int*)addr, __float_as_int(value));
    else
        atomicMin((unsigned int*)addr, __float_as_uint(value));
}

__device__ __forceinline__ float edge_logit(const int* __restrict__ e32, int t, int& s, int& d) {
    if (t < EE) {
        s = edge_src(e32, t);
        d = edge_dst(e32, t);
    } else {
        s = d = t - EE;
    }
    float e = g_as[s] + g_ad[d];
    return (e >= 0.f) ? e : 0.2f * e;  // leaky 0.2
}

__global__ void edge_max(const int* __restrict__ e32) {
    int t = blockIdx.x * blockDim.x + threadIdx.x;
    if (t >= EE + NN) return;
    int s, d;
    float e = edge_logit(e32, t, s, d);
    atomicMaxF(&g_m[d], e);
}

__global__ void edge_expsum(const int* __restrict__ e32) {
    int t = blockIdx.x * blockDim.x + threadIdx.x;
    if (t >= EE + NN) return;
    int s, d;
    float e = edge_logit(e32, t, s, d);
    float ex = __expf(e - g_m[d]);
    g_e[t] = ex;
    atomicAdd(&g_den[d], ex);
}

// ---------------- GAT: init agg with self-loop contribution ----------------
__global__ void agg_init_gat() {
    int idx = blockIdx.x * blockDim.x + threadIdx.x;
    if (idx >= NN * CC) return;
    int n = idx >> 7;
    float alpha = g_e[EE + n] / g_den[n];
    g_agg[idx] = g_h[idx] * alpha;
}

// ---------------- GAT scatter over real edges: warp per edge ----------------
__global__ void __launch_bounds__(256) scatter_gat(const int* __restrict__ e32) {
    int warp = (blockIdx.x * blockDim.x + threadIdx.x) >> 5;
    if (warp >= EE) return;
    int lane = threadIdx.x & 31;
    int s = edge_src(e32, warp);
    int d = edge_dst(e32, warp);
    float alpha = g_e[warp] / g_den[d];
    float4 v = ((const float4*)(g_h + (size_t)s * 128))[lane];
    v.x *= alpha; v.y *= alpha; v.z *= alpha; v.w *= alpha;
    atomicAdd(((float4*)(g_agg + (size_t)d * 128)) + lane, v);
}

// ---------------- launch ----------------
extern "C" void kernel_launch(void* const* d_in, const int* in_sizes, int n_in,
                              void* d_out, int out_size) {
    const float* x = (const float*)d_in[0];
    const int* e32 = (const int*)d_in[1];
    const float* W1 = (const float*)d_in[2];
    const float* b1 = (const float*)d_in[3];
    const float* gn_w = (const float*)d_in[4];
    const float* gn_b = (const float*)d_in[5];
    const float* gn_ms = (const float*)d_in[6];
    const float* Wg = (const float*)d_in[7];
    const float* bg = (const float*)d_in[8];
    const float* att_src = (const float*)d_in[9];
    const float* att_dst = (const float*)d_in[10];
    float* out = (float*)d_out;

    const int TPB = 256;
    const int nb_node = (NN + TPB - 1) / TPB;
    const int nb_edge = (EE + TPB - 1) / TPB;
    const int nb_edgeN = (EE + NN + TPB - 1) / TPB;
    const int warps_per_blk = TPB / 32;
    const int nb_warp_edge = (EE + warps_per_blk - 1) / warps_per_blk;
    const int nb_warp_node = (NN + warps_per_blk - 1) / warps_per_blk;
    const int nb_elem = (NN * CC + TPB - 1) / TPB;
    const int gemm_blocks = (NN + 63) / 64;

    detect_dtype<<<1, 256>>>(e32);

    // ---- Phase A: GCN ----
    init_deg_kernel<<<nb_node, TPB>>>();
    count_deg_kernel<<<nb_edge, TPB>>>(e32);
    dinv_kernel<<<nb_node, TPB>>>();
    gemm128_A<<<gemm_blocks, 256>>>(x, W1);
    agg_init_gcn<<<nb_elem, TPB>>>();
    scatter_gcn<<<nb_warp_edge, TPB>>>(e32);
    zero_stats<<<1, 256>>>();
    colstats<<<512, 256>>>(b1);
    finalize_A<<<nb_elem, TPB>>>(x, b1, gn_w, gn_b, gn_ms);

    // ---- Phase B: GAT ----
    gemm128_B<<<gemm_blocks, 256>>>(Wg);
    attndot<<<nb_warp_node, TPB>>>(att_src, att_dst);
    init_gat_kernel<<<nb_node, TPB>>>();
    edge_max<<<nb_edgeN, TPB>>>(e32);
    edge_expsum<<<nb_edgeN, TPB>>>(e32);
    agg_init_gat<<<nb_elem, TPB>>>();
    scatter_gat<<<nb_warp_edge, TPB>>>(e32);
    zero_stats<<<1, 256>>>();
    colstats<<<512, 256>>>(bg);
    finalize_B<<<nb_elem, TPB>>>(bg, gn_w, gn_b, gn_ms, out);
}

// round 6
// speedup vs baseline: 1.5649x; 1.5649x over previous
#include <cuda_runtime.h>
#include <cstdint>

#define NN 100000
#define EE 1600000
#define CC 128
#define EPS_ 1e-5f
#define NBLK ((NN + 255) / 256)   // 391

// ---------------- scratch (static device globals; no allocation) ----------------
__device__ __align__(16) float g_h[(size_t)NN * CC];     // GEMM output / message features
__device__ __align__(16) float g_agg[(size_t)NN * CC];   // aggregation accumulator
__device__ __align__(16) float g_x1[(size_t)NN * CC];    // x after first block
__device__ float g_dinv[NN];
__device__ float g_as[NN];
__device__ float g_ad[NN];
__device__ float g_stats[2 * CC];          // [0,128): col sum; [128,256): col sumsq
__device__ int g_is64;                     // 1 if edges buffer is int64, 0 if int32
// CSR by destination (self-loops NOT stored; handled analytically)
__device__ int g_degc[NN];                 // incoming-edge count (excl self)
__device__ int g_rowstart[NN];             // exclusive prefix of degc
__device__ int g_cur[NN];                  // fill cursors
__device__ int g_bsum[NBLK + 1];
__device__ int g_boff[NBLK + 1];
__device__ int g_csrc[EE];                 // src node per CSR slot (int32)

// ---------------- edges dtype detection ----------------
__global__ void detect_dtype(const int* __restrict__ e32) {
    __shared__ int ok[256];
    int t = threadIdx.x;
    int all0 = 1;
#pragma unroll
    for (int i = 0; i < 2; i++) {
        int idx = 2 * (t + i * 256) + 1;
        if (e32[idx] != 0) all0 = 0;
    }
    ok[t] = all0;
    __syncthreads();
    for (int s = 128; s; s >>= 1) {
        if (t < s) ok[t] &= ok[t + s];
        __syncthreads();
    }
    if (t == 0) g_is64 = ok[0];
}

__device__ __forceinline__ int edge_src(const int* __restrict__ e32, int t) {
    return g_is64 ? e32[2 * t] : e32[t];
}
__device__ __forceinline__ int edge_dst(const int* __restrict__ e32, int t) {
    return g_is64 ? e32[2 * (EE + t)] : e32[EE + t];
}

// ---------------- CSR build ----------------
__global__ void zero_counts() {
    int i = blockIdx.x * blockDim.x + threadIdx.x;
    if (i < NN) g_degc[i] = 0;
}

__global__ void count_deg_kernel(const int* __restrict__ e32) {
    int t = blockIdx.x * blockDim.x + threadIdx.x;
    if (t < EE) atomicAdd(&g_degc[edge_dst(e32, t)], 1);
}

__global__ void dinv_kernel() {
    int i = blockIdx.x * blockDim.x + threadIdx.x;
    if (i < NN) g_dinv[i] = rsqrtf((float)(g_degc[i] + 1));
}

// block-local exclusive scan of degc; per-block totals to g_bsum
__global__ void scan1() {
    __shared__ int sm[256];
    int b = blockIdx.x, t = threadIdx.x;
    int idx = b * 256 + t;
    int v = (idx < NN) ? g_degc[idx] : 0;
    sm[t] = v;
    __syncthreads();
    // Hillis-Steele inclusive
    for (int o = 1; o < 256; o <<= 1) {
        int add = (t >= o) ? sm[t - o] : 0;
        __syncthreads();
        sm[t] += add;
        __syncthreads();
    }
    if (idx < NN) g_rowstart[idx] = sm[t] - v;   // exclusive within block
    if (t == 255) g_bsum[b] = sm[255];
}

// scan block sums (NBLK values) in one block
__global__ void scan2() {
    __shared__ int sm[512];
    int t = threadIdx.x;
    int v = (t < NBLK) ? g_bsum[t] : 0;
    sm[t] = v;
    __syncthreads();
    for (int o = 1; o < 512; o <<= 1) {
        int add = (t >= o) ? sm[t - o] : 0;
        __syncthreads();
        sm[t] += add;
        __syncthreads();
    }
    if (t < NBLK) g_boff[t] = sm[t] - v;   // exclusive
}

__global__ void scan3() {
    int idx = blockIdx.x * blockDim.x + threadIdx.x;
    if (idx < NN) {
        g_rowstart[idx] += g_boff[blockIdx.x * 256 / 256 == 0 ? blockIdx.x : blockIdx.x];  // = g_boff[blockIdx.x]
        g_cur[idx] = 0;
    }
}

__global__ void fill_csr(const int* __restrict__ e32) {
    int t = blockIdx.x * blockDim.x + threadIdx.x;
    if (t >= EE) return;
    int s = edge_src(e32, t);
    int d = edge_dst(e32, t);
    int pos = g_rowstart[d] + atomicAdd(&g_cur[d], 1);
    g_csrc[pos] = s;
}

// ---------------- GEMM core: g_h[n,128] = IN[n,128] @ W[128,128] ----------------
template <bool FROM_X1>
__device__ __forceinline__ void gemm128_body(const float* __restrict__ Xext,
                                             const float* __restrict__ W) {
    __shared__ float Xs[64][33];
    __shared__ float Ws[32][128];
    const float* X = FROM_X1 ? g_x1 : Xext;
    int row0 = blockIdx.x * 64;
    int tx = threadIdx.x & 15;
    int ty = threadIdx.x >> 4;
    float acc[4][8];
#pragma unroll
    for (int i = 0; i < 4; i++)
#pragma unroll
        for (int j = 0; j < 8; j++) acc[i][j] = 0.f;

    for (int kt = 0; kt < 128; kt += 32) {
#pragma unroll
        for (int i = 0; i < 8; i++) {
            int idx = threadIdx.x + i * 256;
            int r = idx >> 5, c = idx & 31;
            int gr = row0 + r;
            Xs[r][c] = (gr < NN) ? X[(size_t)gr * 128 + kt + c] : 0.f;
        }
#pragma unroll
        for (int i = 0; i < 16; i++) {
            int idx = threadIdx.x + i * 256;
            int r = idx >> 7, c = idx & 127;
            Ws[r][c] = W[(size_t)(kt + r) * 128 + c];
        }
        __syncthreads();
#pragma unroll
        for (int k = 0; k < 32; k++) {
            float a[4], b[8];
#pragma unroll
            for (int i = 0; i < 4; i++) a[i] = Xs[ty * 4 + i][k];
#pragma unroll
            for (int j = 0; j < 8; j++) b[j] = Ws[k][j * 16 + tx];
#pragma unroll
            for (int i = 0; i < 4; i++)
#pragma unroll
                for (int j = 0; j < 8; j++) acc[i][j] = fmaf(a[i], b[j], acc[i][j]);
        }
        __syncthreads();
    }
#pragma unroll
    for (int i = 0; i < 4; i++) {
        int gr = row0 + ty * 4 + i;
        if (gr < NN) {
#pragma unroll
            for (int j = 0; j < 8; j++) g_h[(size_t)gr * 128 + j * 16 + tx] = acc[i][j];
        }
    }
}

__global__ void __launch_bounds__(256) gemm128_A(const float* __restrict__ X,
                                                 const float* __restrict__ W) {
    gemm128_body<false>(X, W);
}
__global__ void __launch_bounds__(256) gemm128_B(const float* __restrict__ W) {
    gemm128_body<true>(nullptr, W);
}

// ---------------- GCN gather: warp per dst node ----------------
__global__ void __launch_bounds__(256) gather_gcn() {
    int d = (blockIdx.x * blockDim.x + threadIdx.x) >> 5;
    if (d >= NN) return;
    int lane = threadIdx.x & 31;
    int beg = g_rowstart[d];
    int num = g_degc[d];
    float dd = g_dinv[d];
    const float4* hrow_d = (const float4*)(g_h + (size_t)d * 128);
    float4 acc = hrow_d[lane];
    float w0 = dd * dd;
    acc.x *= w0; acc.y *= w0; acc.z *= w0; acc.w *= w0;
    for (int j = beg; j < beg + num; j++) {
        int s = g_csrc[j];
        float w = g_dinv[s] * dd;
        float4 v = ((const float4*)(g_h + (size_t)s * 128))[lane];
        acc.x = fmaf(v.x, w, acc.x);
        acc.y = fmaf(v.y, w, acc.y);
        acc.z = fmaf(v.z, w, acc.z);
        acc.w = fmaf(v.w, w, acc.w);
    }
    ((float4*)(g_agg + (size_t)d * 128))[lane] = acc;
}

// ---------------- column stats ----------------
__global__ void zero_stats() {
    int i = threadIdx.x;
    if (i < 2 * CC) g_stats[i] = 0.f;
}

__global__ void colstats(const float* __restrict__ bias) {
    __shared__ float s1[256], s2[256];
    int c = threadIdx.x & 127;
    int half = threadIdx.x >> 7;
    float b = bias[c];
    float acc = 0.f, acc2 = 0.f;
    for (int r = blockIdx.x * 2 + half; r < NN; r += gridDim.x * 2) {
        float t = g_agg[(size_t)r * 128 + c] + b;
        acc += t;
        acc2 += t * t;
    }
    s1[threadIdx.x] = acc;
    s2[threadIdx.x] = acc2;
    __syncthreads();
    if (half == 0) {
        atomicAdd(&g_stats[c], s1[c] + s1[c + 128]);
        atomicAdd(&g_stats[128 + c], s2[c] + s2[c + 128]);
    }
}

// ---------------- finalize: GraphNorm + LeakyReLU + residual ----------------
template <bool PHASE_B>
__device__ __forceinline__ void finalize_body(const float* __restrict__ xin_ext,
                                              const float* __restrict__ bias,
                                              const float* __restrict__ gw,
                                              const float* __restrict__ gb,
                                              const float* __restrict__ gms,
                                              float* __restrict__ xout_ext) {
    int idx = blockIdx.x * blockDim.x + threadIdx.x;
    if (idx >= NN * CC) return;
    int c = idx & 127;
    float t = g_agg[idx] + bias[c];
    const float invn = 1.0f / (float)NN;
    float mean = g_stats[c] * invn;
    float a = gms[c] * mean;
    float var = g_stats[128 + c] * invn - 2.f * a * mean + a * a;
    float y = gw[c] * (t - a) * rsqrtf(var + EPS_) + gb[c];
    y = (y >= 0.f) ? y : 0.01f * y;
    float xv = PHASE_B ? g_x1[idx] : xin_ext[idx];
    float r = xv + y;
    if (PHASE_B) xout_ext[idx] = r;
    else g_x1[idx] = r;
}

__global__ void finalize_A(const float* __restrict__ xin, const float* __restrict__ bias,
                           const float* __restrict__ gw, const float* __restrict__ gb,
                           const float* __restrict__ gms) {
    finalize_body<false>(xin, bias, gw, gb, gms, nullptr);
}
__global__ void finalize_B(const float* __restrict__ bias, const float* __restrict__ gw,
                           const float* __restrict__ gb, const float* __restrict__ gms,
                           float* __restrict__ xout) {
    finalize_body<true>(nullptr, bias, gw, gb, gms, xout);
}

// ---------------- GAT attention dots: warp per node ----------------
__global__ void attndot(const float* __restrict__ att_src, const float* __restrict__ att_dst) {
    int warp = (blockIdx.x * blockDim.x + threadIdx.x) >> 5;
    if (warp >= NN) return;
    int lane = threadIdx.x & 31;
    float4 hv = ((const float4*)(g_h + (size_t)warp * 128))[lane];
    float4 av = ((const float4*)att_src)[lane];
    float4 dv = ((const float4*)att_dst)[lane];
    float ps = hv.x * av.x + hv.y * av.y + hv.z * av.z + hv.w * av.w;
    float pd = hv.x * dv.x + hv.y * dv.y + hv.z * dv.z + hv.w * dv.w;
#pragma unroll
    for (int o = 16; o; o >>= 1) {
        ps += __shfl_xor_sync(0xffffffffu, ps, o);
        pd += __shfl_xor_sync(0xffffffffu, pd, o);
    }
    if (lane == 0) {
        g_as[warp] = ps;
        g_ad[warp] = pd;
    }
}

// ---------------- GAT gather (fused softmax): warp per dst node ----------------
__global__ void __launch_bounds__(256) gather_gat() {
    int d = (blockIdx.x * blockDim.x + threadIdx.x) >> 5;
    if (d >= NN) return;
    int lane = threadIdx.x & 31;
    int beg = g_rowstart[d];
    int end = beg + g_degc[d];
    float add = g_ad[d];
    float es = g_as[d] + add;                 // self logit
    es = (es >= 0.f) ? es : 0.2f * es;

    // 1) segment max (lanes stride edges)
    float m = es;
    for (int j = beg + lane; j < end; j += 32) {
        float e = g_as[g_csrc[j]] + add;
        e = (e >= 0.f) ? e : 0.2f * e;
        m = fmaxf(m, e);
    }
#pragma unroll
    for (int o = 16; o; o >>= 1) m = fmaxf(m, __shfl_xor_sync(0xffffffffu, m, o));

    // 2) denom
    float den = __expf(es - m);
    {
        float part = 0.f;
        for (int j = beg + lane; j < end; j += 32) {
            float e = g_as[g_csrc[j]] + add;
            e = (e >= 0.f) ? e : 0.2f * e;
            part += __expf(e - m);
        }
#pragma unroll
        for (int o = 16; o; o >>= 1) part += __shfl_xor_sync(0xffffffffu, part, o);
        den += part;
    }
    float rden = 1.0f / den;

    // 3) weighted accumulate (warp cooperates per edge; lane owns 4 channels)
    float4 acc = ((const float4*)(g_h + (size_t)d * 128))[lane];
    float ws = __expf(es - m);
    acc.x *= ws; acc.y *= ws; acc.z *= ws; acc.w *= ws;
    for (int j = beg; j < end; j++) {
        int s = g_csrc[j];
        float e = g_as[s] + add;
        e = (e >= 0.f) ? e : 0.2f * e;
        float w = __expf(e - m);
        float4 v = ((const float4*)(g_h + (size_t)s * 128))[lane];
        acc.x = fmaf(v.x, w, acc.x);
        acc.y = fmaf(v.y, w, acc.y);
        acc.z = fmaf(v.z, w, acc.z);
        acc.w = fmaf(v.w, w, acc.w);
    }
    acc.x *= rden; acc.y *= rden; acc.z *= rden; acc.w *= rden;
    ((float4*)(g_agg + (size_t)d * 128))[lane] = acc;
}

// ---------------- launch ----------------
extern "C" void kernel_launch(void* const* d_in, const int* in_sizes, int n_in,
                              void* d_out, int out_size) {
    const float* x = (const float*)d_in[0];
    const int* e32 = (const int*)d_in[1];
    const float* W1 = (const float*)d_in[2];
    const float* b1 = (const float*)d_in[3];
    const float* gn_w = (const float*)d_in[4];
    const float* gn_b = (const float*)d_in[5];
    const float* gn_ms = (const float*)d_in[6];
    const float* Wg = (const float*)d_in[7];
    const float* bg = (const float*)d_in[8];
    const float* att_src = (const float*)d_in[9];
    const float* att_dst = (const float*)d_in[10];
    float* out = (float*)d_out;

    const int TPB = 256;
    const int nb_node = NBLK;
    const int nb_edge = (EE + TPB - 1) / TPB;
    const int nb_warp_node = (NN * 32 + TPB - 1) / TPB;
    const int nb_elem = (NN * CC + TPB - 1) / TPB;
    const int gemm_blocks = (NN + 63) / 64;

    detect_dtype<<<1, 256>>>(e32);

    // ---- CSR build (shared by both phases) ----
    zero_counts<<<nb_node, TPB>>>();
    count_deg_kernel<<<nb_edge, TPB>>>(e32);
    dinv_kernel<<<nb_node, TPB>>>();
    scan1<<<nb_node, 256>>>();
    scan2<<<1, 512>>>();
    scan3<<<nb_node, 256>>>();
    fill_csr<<<nb_edge, TPB>>>(e32);

    // ---- Phase A: GCN ----
    gemm128_A<<<gemm_blocks, 256>>>(x, W1);
    gather_gcn<<<nb_warp_node, TPB>>>();
    zero_stats<<<1, 256>>>();
    colstats<<<512, 256>>>(b1);
    finalize_A<<<nb_elem, TPB>>>(x, b1, gn_w, gn_b, gn_ms);

    // ---- Phase B: GAT ----
    gemm128_B<<<gemm_blocks, 256>>>(Wg);
    attndot<<<nb_warp_node, TPB>>>(att_src, att_dst);
    gather_gat<<<nb_warp_node, TPB>>>();
    zero_stats<<<1, 256>>>();
    colstats<<<512, 256>>>(bg);
    finalize_B<<<nb_elem, TPB>>>(bg, gn_w, gn_b, gn_ms, out);
}